// round 1
// baseline (speedup 1.0000x reference)
#include <cuda_runtime.h>
#include <cstdint>

#define NODES 100000
#define F0 128
#define F1 64
#define F2 32

// ---- scratch (static device globals: allocation-free) ----
__device__ float d_deg[NODES];
__device__ float d_dinv[NODES];
__device__ float d_g1[(size_t)NODES * F1];    // (x@W1)*dinv  (gather source, layer1)
__device__ float d_acc1[(size_t)NODES * F1];  // scatter accumulator, seeded with self-loop g1
__device__ float d_g2[(size_t)NODES * F2];    // (v@W2)*dinv  (gather source, layer2)

// ---------------- degree / dinv ----------------
__global__ void k_init_deg(int n) {
    int i = blockIdx.x * blockDim.x + threadIdx.x;
    if (i < n) d_deg[i] = 1.0f;  // self-loop pre-counted
}

__global__ void k_count_deg(const int* __restrict__ dst, int e) {
    int i = blockIdx.x * blockDim.x + threadIdx.x;
    if (i < e) atomicAdd(&d_deg[dst[i]], 1.0f);
}

__global__ void k_dinv(int n) {
    int i = blockIdx.x * blockDim.x + threadIdx.x;
    if (i < n) d_dinv[i] = rsqrtf(d_deg[i]);
}

// ---------------- GEMM1: g1 = (x @ W1) * dinv ; acc1 = g1 (self-loop seed) ----
// 256 threads, 64 nodes x 64 features per block, 4x4 register tile per thread.
__global__ void k_gemm1(const float* __restrict__ x, const float* __restrict__ W, int n) {
    __shared__ float xs[64][65];
    __shared__ float ws[64][65];
    int tid = threadIdx.x;
    int tx = tid & 15, ty = tid >> 4;
    int nodeBase = blockIdx.x * 64;
    float acc[4][4] = {};

#pragma unroll
    for (int kc = 0; kc < F0; kc += 64) {
#pragma unroll
        for (int r = 0; r < 4; ++r) {
            int row = ty + r * 16;      // 0..63
            int col = tx * 4;           // 0..60
            int node = nodeBase + row;
            float4 v = make_float4(0.f, 0.f, 0.f, 0.f);
            if (node < n) v = *(const float4*)(x + (size_t)node * F0 + kc + col);
            xs[row][col + 0] = v.x; xs[row][col + 1] = v.y;
            xs[row][col + 2] = v.z; xs[row][col + 3] = v.w;
            float4 w = *(const float4*)(W + (size_t)(kc + row) * F1 + col);
            ws[row][col + 0] = w.x; ws[row][col + 1] = w.y;
            ws[row][col + 2] = w.z; ws[row][col + 3] = w.w;
        }
        __syncthreads();
#pragma unroll
        for (int k = 0; k < 64; ++k) {
            float a0 = xs[4 * ty + 0][k];
            float a1 = xs[4 * ty + 1][k];
            float a2 = xs[4 * ty + 2][k];
            float a3 = xs[4 * ty + 3][k];
            float b0 = ws[k][4 * tx + 0];
            float b1 = ws[k][4 * tx + 1];
            float b2 = ws[k][4 * tx + 2];
            float b3 = ws[k][4 * tx + 3];
            acc[0][0] += a0 * b0; acc[0][1] += a0 * b1; acc[0][2] += a0 * b2; acc[0][3] += a0 * b3;
            acc[1][0] += a1 * b0; acc[1][1] += a1 * b1; acc[1][2] += a1 * b2; acc[1][3] += a1 * b3;
            acc[2][0] += a2 * b0; acc[2][1] += a2 * b1; acc[2][2] += a2 * b2; acc[2][3] += a2 * b3;
            acc[3][0] += a3 * b0; acc[3][1] += a3 * b1; acc[3][2] += a3 * b2; acc[3][3] += a3 * b3;
        }
        __syncthreads();
    }

#pragma unroll
    for (int i = 0; i < 4; ++i) {
        int node = nodeBase + 4 * ty + i;
        if (node < n) {
            float dv = d_dinv[node];
            float4 v;
            v.x = acc[i][0] * dv; v.y = acc[i][1] * dv;
            v.z = acc[i][2] * dv; v.w = acc[i][3] * dv;
            *(float4*)(d_g1 + (size_t)node * F1 + 4 * tx) = v;
            *(float4*)(d_acc1 + (size_t)node * F1 + 4 * tx) = v;
        }
    }
}

// ---------------- Scatter layer 1: acc1[dst] += g1[src]  (64 f32 per edge) ---
// 16 threads per edge, one float4 + red.global.add.v4 each.
__global__ void k_scatter64(const int* __restrict__ src, const int* __restrict__ dst, int e) {
    long gid = (long)blockIdx.x * blockDim.x + threadIdx.x;
    long eid = gid >> 4;
    if (eid >= e) return;
    int i = (int)(gid & 15);
    int s = __ldg(&src[eid]);
    int d = __ldg(&dst[eid]);
    float4 v = __ldg((const float4*)(d_g1 + (size_t)s * F1 + i * 4));
    float* p = d_acc1 + (size_t)d * F1 + i * 4;
    asm volatile("red.global.add.v4.f32 [%0], {%1,%2,%3,%4};"
                 :: "l"(p), "f"(v.x), "f"(v.y), "f"(v.z), "f"(v.w)
                 : "memory");
}

// ---------------- Layer 2 fused: v=relu(acc1*dinv+b1); g2=(v@W2)*dinv; out=g2 seed ----
__global__ void k_layer2(const float* __restrict__ b1, const float* __restrict__ W2,
                         float* __restrict__ out, int n) {
    __shared__ float vs[64][65];
    __shared__ float ws[64][33];
    int tid = threadIdx.x;
    int tx = tid & 15, ty = tid >> 4;
    int nodeBase = blockIdx.x * 64;

#pragma unroll
    for (int r = 0; r < 4; ++r) {
        int row = ty + r * 16;
        int col = tx * 4;
        int node = nodeBase + row;
        float4 v = make_float4(0.f, 0.f, 0.f, 0.f);
        if (node < n) {
            float dv = d_dinv[node];
            float4 a = *(const float4*)(d_acc1 + (size_t)node * F1 + col);
            v.x = fmaxf(fmaf(a.x, dv, __ldg(&b1[col + 0])), 0.f);
            v.y = fmaxf(fmaf(a.y, dv, __ldg(&b1[col + 1])), 0.f);
            v.z = fmaxf(fmaf(a.z, dv, __ldg(&b1[col + 2])), 0.f);
            v.w = fmaxf(fmaf(a.w, dv, __ldg(&b1[col + 3])), 0.f);
        }
        vs[row][col + 0] = v.x; vs[row][col + 1] = v.y;
        vs[row][col + 2] = v.z; vs[row][col + 3] = v.w;
    }
    // W2: 64x32 = 512 float4s
    for (int c = tid; c < 512; c += 256) {
        int row = c >> 3;
        int col = (c & 7) * 4;
        float4 w = *(const float4*)(W2 + row * F2 + col);
        ws[row][col + 0] = w.x; ws[row][col + 1] = w.y;
        ws[row][col + 2] = w.z; ws[row][col + 3] = w.w;
    }
    __syncthreads();

    float acc[4][2] = {};
#pragma unroll
    for (int k = 0; k < 64; ++k) {
        float a0 = vs[4 * ty + 0][k];
        float a1 = vs[4 * ty + 1][k];
        float a2 = vs[4 * ty + 2][k];
        float a3 = vs[4 * ty + 3][k];
        float c0 = ws[k][2 * tx + 0];
        float c1 = ws[k][2 * tx + 1];
        acc[0][0] += a0 * c0; acc[0][1] += a0 * c1;
        acc[1][0] += a1 * c0; acc[1][1] += a1 * c1;
        acc[2][0] += a2 * c0; acc[2][1] += a2 * c1;
        acc[3][0] += a3 * c0; acc[3][1] += a3 * c1;
    }

#pragma unroll
    for (int i = 0; i < 4; ++i) {
        int node = nodeBase + 4 * ty + i;
        if (node < n) {
            float dv = d_dinv[node];
            float2 v = make_float2(acc[i][0] * dv, acc[i][1] * dv);
            *(float2*)(d_g2 + (size_t)node * F2 + 2 * tx) = v;
            *(float2*)(out + (size_t)node * F2 + 2 * tx) = v;  // self-loop seed
        }
    }
}

// ---------------- Scatter layer 2: out[dst] += g2[src]  (32 f32 per edge) ----
__global__ void k_scatter32(const int* __restrict__ src, const int* __restrict__ dst,
                            float* __restrict__ out, int e) {
    long gid = (long)blockIdx.x * blockDim.x + threadIdx.x;
    long eid = gid >> 3;
    if (eid >= e) return;
    int i = (int)(gid & 7);
    int s = __ldg(&src[eid]);
    int d = __ldg(&dst[eid]);
    float4 v = __ldg((const float4*)(d_g2 + (size_t)s * F2 + i * 4));
    float* p = out + (size_t)d * F2 + i * 4;
    asm volatile("red.global.add.v4.f32 [%0], {%1,%2,%3,%4};"
                 :: "l"(p), "f"(v.x), "f"(v.y), "f"(v.z), "f"(v.w)
                 : "memory");
}

// ---------------- final: out = out*dinv + b2 ----------------
__global__ void k_final(float* __restrict__ out, const float* __restrict__ b2, int n) {
    int i = blockIdx.x * blockDim.x + threadIdx.x;
    if (i < n * F2) {
        out[i] = out[i] * d_dinv[i >> 5] + __ldg(&b2[i & 31]);
    }
}

extern "C" void kernel_launch(void* const* d_in, const int* in_sizes, int n_in,
                              void* d_out, int out_size) {
    const float* x  = (const float*)d_in[0];
    const int*   ei = (const int*)d_in[1];
    const float* W1 = (const float*)d_in[2];
    const float* b1 = (const float*)d_in[3];
    const float* W2 = (const float*)d_in[4];
    const float* b2 = (const float*)d_in[5];
    float* out = (float*)d_out;

    int n = in_sizes[0] / F0;   // 100000
    int e = in_sizes[1] / 2;    // 1600000
    const int* src = ei;
    const int* dst = ei + e;

    k_init_deg<<<(n + 255) / 256, 256>>>(n);
    k_count_deg<<<(e + 255) / 256, 256>>>(dst, e);
    k_dinv<<<(n + 255) / 256, 256>>>(n);

    k_gemm1<<<(n + 63) / 64, 256>>>(x, W1, n);

    long t1 = (long)e * 16;
    k_scatter64<<<(unsigned)((t1 + 255) / 256), 256>>>(src, dst, e);

    k_layer2<<<(n + 63) / 64, 256>>>(b1, W2, out, n);

    long t2 = (long)e * 8;
    k_scatter32<<<(unsigned)((t2 + 255) / 256), 256>>>(src, dst, out, e);

    k_final<<<(n * F2 + 255) / 256, 256>>>(out, b2, n);
}

// round 2
// speedup vs baseline: 1.6071x; 1.6071x over previous
#include <cuda_runtime.h>
#include <cstdint>

#define NODES 100000
#define EMAX  1600000
#define F0 128
#define F1 64
#define F2 32
#define NB_SCAN 196          // ceil(100000/512)
#define NPAD (NB_SCAN*512)   // 100352

// ---- scratch (static device globals: allocation-free) ----
__device__ int   d_degi[NODES];
__device__ int   d_loc[NPAD];
__device__ int   d_part[NB_SCAN];
__device__ int   d_partx[NB_SCAN];
__device__ int   d_off[NODES + 1];
__device__ int   d_pos[NODES];
__device__ int   d_csr[EMAX];
__device__ float d_dinv[NODES];
__device__ float d_g1[(size_t)NODES * F1];
__device__ float d_h1[(size_t)NODES * F1];
__device__ float d_g2[(size_t)NODES * F2];

// ================= degree histogram =================
__global__ void k_zero(int n) {
    int i = blockIdx.x * blockDim.x + threadIdx.x;
    if (i < n) d_degi[i] = 0;
}

__global__ void k_count(const int* __restrict__ dst, int e) {
    int i = blockIdx.x * blockDim.x + threadIdx.x;
    if (i < e) atomicAdd(&d_degi[dst[i]], 1);
}

// ================= 3-pass exclusive scan =================
__global__ void k_scan1(int n) {
    __shared__ int s[512];
    int i = blockIdx.x * 512 + threadIdx.x;
    int v = (i < n) ? d_degi[i] : 0;
    s[threadIdx.x] = v;
    __syncthreads();
#pragma unroll
    for (int off = 1; off < 512; off <<= 1) {
        int t = (threadIdx.x >= off) ? s[threadIdx.x - off] : 0;
        __syncthreads();
        s[threadIdx.x] += t;
        __syncthreads();
    }
    d_loc[i] = s[threadIdx.x] - v;  // exclusive
    if (threadIdx.x == 511) d_part[blockIdx.x] = s[511];
}

__global__ void k_scan2(int nb, int n, int e) {
    __shared__ int s[256];
    int v = (threadIdx.x < nb) ? d_part[threadIdx.x] : 0;
    s[threadIdx.x] = v;
    __syncthreads();
#pragma unroll
    for (int off = 1; off < 256; off <<= 1) {
        int t = (threadIdx.x >= off) ? s[threadIdx.x - off] : 0;
        __syncthreads();
        s[threadIdx.x] += t;
        __syncthreads();
    }
    if (threadIdx.x < nb) d_partx[threadIdx.x] = s[threadIdx.x] - v;
    if (threadIdx.x == 0) d_off[n] = e;
}

__global__ void k_scan3(int n) {
    int i = blockIdx.x * 512 + threadIdx.x;
    if (i < n) {
        int o = d_loc[i] + d_partx[blockIdx.x];
        d_off[i] = o;
        d_pos[i] = o;
        d_dinv[i] = rsqrtf(1.0f + (float)d_degi[i]);  // +1 self-loop
    }
}

// ================= CSR fill =================
__global__ void k_fill(const int* __restrict__ src, const int* __restrict__ dst, int e) {
    int i = blockIdx.x * blockDim.x + threadIdx.x;
    if (i < e) {
        int d = dst[i];
        int p = atomicAdd(&d_pos[d], 1);
        d_csr[p] = src[i];
    }
}

// ================= GEMM1: g1 = (x @ W1) * dinv =================
// block: 128 nodes x 64 cols, 256 threads, 8x4 register tile.
// x-tile stored transposed (k-major) with swizzle g' = g ^ ((k>>2)&7) at float4
// granularity: conflict-free staging stores AND conflict-free LDS.128 A-loads.
__global__ void k_gemm1(const float* __restrict__ x, const float* __restrict__ W, int n) {
    __shared__ float4 xs4[32 * 33];
    __shared__ float  ws[32][68];
    int tid = threadIdx.x;
    int tx = tid & 15, ty = tid >> 4;
    int nodeBase = blockIdx.x * 128;
    float acc[8][4] = {};

    for (int kc = 0; kc < F0; kc += 32) {
        // stage x (transposed + swizzled)
#pragma unroll
        for (int i = 0; i < 4; ++i) {
            int flat = i * 256 + tid;
            int row = flat >> 3;   // 0..127
            int c4  = flat & 7;    // k group
            int node = nodeBase + row;
            float4 v = make_float4(0.f, 0.f, 0.f, 0.f);
            if (node < n) v = __ldg((const float4*)(x + (size_t)node * F0 + kc + 4 * c4));
            int g = row >> 2, el = row & 3;
            const float vv[4] = {v.x, v.y, v.z, v.w};
#pragma unroll
            for (int j = 0; j < 4; ++j) {
                int k = 4 * c4 + j;
                float* p = (float*)&xs4[k * 33 + (g ^ ((k >> 2) & 7))];
                p[el] = vv[j];
            }
        }
        // stage W
#pragma unroll
        for (int i = 0; i < 2; ++i) {
            int flat = i * 256 + tid;
            int k = flat >> 4;
            int c4 = flat & 15;
            float4 w = __ldg((const float4*)(W + (size_t)(kc + k) * F1 + 4 * c4));
            *(float4*)&ws[k][4 * c4] = w;
        }
        __syncthreads();
#pragma unroll
        for (int k = 0; k < 32; ++k) {
            int swz = (k >> 2) & 7;
            float4 A0 = xs4[k * 33 + ((2 * ty) ^ swz)];
            float4 A1 = xs4[k * 33 + ((2 * ty + 1) ^ swz)];
            float4 B  = *(const float4*)&ws[k][4 * tx];
            float a[8] = {A0.x, A0.y, A0.z, A0.w, A1.x, A1.y, A1.z, A1.w};
            float b[4] = {B.x, B.y, B.z, B.w};
#pragma unroll
            for (int m = 0; m < 8; ++m)
#pragma unroll
                for (int q = 0; q < 4; ++q)
                    acc[m][q] += a[m] * b[q];
        }
        __syncthreads();
    }

#pragma unroll
    for (int m = 0; m < 8; ++m) {
        int node = nodeBase + 8 * ty + m;
        if (node < n) {
            float dv = d_dinv[node];
            float4 o = make_float4(acc[m][0] * dv, acc[m][1] * dv,
                                   acc[m][2] * dv, acc[m][3] * dv);
            *(float4*)(d_g1 + (size_t)node * F1 + 4 * tx) = o;
        }
    }
}

// ================= Gather layer1: h1 = relu((sum_in g1 + g1_self)*dinv + b1) ====
// 16 lanes per node, float4 per lane (64 feats), edge loop unrolled x2.
__global__ void k_gather1(const float* __restrict__ b1, int n) {
    int grp = threadIdx.x >> 4, lane = threadIdx.x & 15;
    int node = blockIdx.x * 16 + grp;
    if (node >= n) return;
    const float4* g1 = (const float4*)d_g1;
    float4 acc = __ldg(&g1[(size_t)node * 16 + lane]);  // self loop
    int beg = d_off[node], end = d_off[node + 1];
    int j = beg;
    for (; j + 2 <= end; j += 2) {
        int s0 = __ldg(&d_csr[j]);
        int s1 = __ldg(&d_csr[j + 1]);
        float4 v0 = __ldg(&g1[(size_t)s0 * 16 + lane]);
        float4 v1 = __ldg(&g1[(size_t)s1 * 16 + lane]);
        acc.x += v0.x + v1.x; acc.y += v0.y + v1.y;
        acc.z += v0.z + v1.z; acc.w += v0.w + v1.w;
    }
    if (j < end) {
        int s = __ldg(&d_csr[j]);
        float4 v = __ldg(&g1[(size_t)s * 16 + lane]);
        acc.x += v.x; acc.y += v.y; acc.z += v.z; acc.w += v.w;
    }
    float dv = d_dinv[node];
    float4 bb = __ldg(&((const float4*)b1)[lane]);
    float4 h;
    h.x = fmaxf(fmaf(acc.x, dv, bb.x), 0.f);
    h.y = fmaxf(fmaf(acc.y, dv, bb.y), 0.f);
    h.z = fmaxf(fmaf(acc.z, dv, bb.z), 0.f);
    h.w = fmaxf(fmaf(acc.w, dv, bb.w), 0.f);
    ((float4*)d_h1)[(size_t)node * 16 + lane] = h;
}

// ================= GEMM2: g2 = (h1 @ W2) * dinv =================
// block: 128 nodes x 32 cols, 256 threads, 8x2 tile. K=64 single chunk.
__global__ void k_gemm2(const float* __restrict__ W2, int n) {
    __shared__ float4 xs4[64 * 33];
    __shared__ float  ws[64][36];
    int tid = threadIdx.x;
    int tx = tid & 15, ty = tid >> 4;
    int nodeBase = blockIdx.x * 128;
    float acc[8][2] = {};

    // stage h1 (128 rows x 64 k) transposed + swizzled
#pragma unroll
    for (int i = 0; i < 8; ++i) {
        int flat = i * 256 + tid;
        int row = flat >> 4;  // 0..127
        int c4  = flat & 15;  // 0..15
        int node = nodeBase + row;
        float4 v = make_float4(0.f, 0.f, 0.f, 0.f);
        if (node < n) v = __ldg((const float4*)(d_h1 + (size_t)node * F1 + 4 * c4));
        int g = row >> 2, el = row & 3;
        const float vv[4] = {v.x, v.y, v.z, v.w};
#pragma unroll
        for (int j = 0; j < 4; ++j) {
            int k = 4 * c4 + j;
            float* p = (float*)&xs4[k * 33 + (g ^ ((k >> 2) & 7))];
            p[el] = vv[j];
        }
    }
    // stage W2 (64 x 32)
#pragma unroll
    for (int i = 0; i < 2; ++i) {
        int flat = i * 256 + tid;
        int k = flat >> 3;   // 0..63
        int c4 = flat & 7;   // 0..7
        float4 w = __ldg((const float4*)(W2 + (size_t)k * F2 + 4 * c4));
        *(float4*)&ws[k][4 * c4] = w;
    }
    __syncthreads();

#pragma unroll
    for (int k = 0; k < 64; ++k) {
        int swz = (k >> 2) & 7;
        float4 A0 = xs4[k * 33 + ((2 * ty) ^ swz)];
        float4 A1 = xs4[k * 33 + ((2 * ty + 1) ^ swz)];
        float b0 = ws[k][2 * tx + 0];
        float b1 = ws[k][2 * tx + 1];
        float a[8] = {A0.x, A0.y, A0.z, A0.w, A1.x, A1.y, A1.z, A1.w};
#pragma unroll
        for (int m = 0; m < 8; ++m) {
            acc[m][0] += a[m] * b0;
            acc[m][1] += a[m] * b1;
        }
    }

#pragma unroll
    for (int m = 0; m < 8; ++m) {
        int node = nodeBase + 8 * ty + m;
        if (node < n) {
            float dv = d_dinv[node];
            float2 o = make_float2(acc[m][0] * dv, acc[m][1] * dv);
            *(float2*)(d_g2 + (size_t)node * F2 + 2 * tx) = o;
        }
    }
}

// ================= Gather layer2: out = (sum_in g2 + g2_self)*dinv + b2 ====
// 8 lanes per node, float4 per lane (32 feats).
__global__ void k_gather2(const float* __restrict__ b2, float* __restrict__ out, int n) {
    int grp = threadIdx.x >> 3, lane = threadIdx.x & 7;
    int node = blockIdx.x * 32 + grp;
    if (node >= n) return;
    const float4* g2 = (const float4*)d_g2;
    float4 acc = __ldg(&g2[(size_t)node * 8 + lane]);  // self loop
    int beg = d_off[node], end = d_off[node + 1];
    int j = beg;
    for (; j + 2 <= end; j += 2) {
        int s0 = __ldg(&d_csr[j]);
        int s1 = __ldg(&d_csr[j + 1]);
        float4 v0 = __ldg(&g2[(size_t)s0 * 8 + lane]);
        float4 v1 = __ldg(&g2[(size_t)s1 * 8 + lane]);
        acc.x += v0.x + v1.x; acc.y += v0.y + v1.y;
        acc.z += v0.z + v1.z; acc.w += v0.w + v1.w;
    }
    if (j < end) {
        int s = __ldg(&d_csr[j]);
        float4 v = __ldg(&g2[(size_t)s * 8 + lane]);
        acc.x += v.x; acc.y += v.y; acc.z += v.z; acc.w += v.w;
    }
    float dv = d_dinv[node];
    float4 bb = __ldg(&((const float4*)b2)[lane]);
    float4 o;
    o.x = fmaf(acc.x, dv, bb.x);
    o.y = fmaf(acc.y, dv, bb.y);
    o.z = fmaf(acc.z, dv, bb.z);
    o.w = fmaf(acc.w, dv, bb.w);
    ((float4*)out)[(size_t)node * 8 + lane] = o;
}

extern "C" void kernel_launch(void* const* d_in, const int* in_sizes, int n_in,
                              void* d_out, int out_size) {
    const float* x  = (const float*)d_in[0];
    const int*   ei = (const int*)d_in[1];
    const float* W1 = (const float*)d_in[2];
    const float* b1 = (const float*)d_in[3];
    const float* W2 = (const float*)d_in[4];
    const float* b2 = (const float*)d_in[5];
    float* out = (float*)d_out;

    int n = in_sizes[0] / F0;   // 100000
    int e = in_sizes[1] / 2;    // 1600000
    const int* src = ei;
    const int* dst = ei + e;
    int nb = (n + 511) / 512;   // 196

    // CSR build
    k_zero<<<(n + 255) / 256, 256>>>(n);
    k_count<<<(e + 255) / 256, 256>>>(dst, e);
    k_scan1<<<nb, 512>>>(n);
    k_scan2<<<1, 256>>>(nb, n, e);
    k_scan3<<<nb, 512>>>(n);
    k_fill<<<(e + 255) / 256, 256>>>(src, dst, e);

    // layer 1
    k_gemm1<<<(n + 127) / 128, 256>>>(x, W1, n);
    k_gather1<<<(n + 15) / 16, 256>>>(b1, n);

    // layer 2
    k_gemm2<<<(n + 127) / 128, 256>>>(W2, n);
    k_gather2<<<(n + 31) / 32, 256>>>(b2, out, n);
}